// round 15
// baseline (speedup 1.0000x reference)
#include <cuda_runtime.h>
#include <math.h>

// out[b,c,h,w] = prod_{p=1..24} cos(x_p + w_p), 5x5 'same' window.
// cos(x+w_p) = cos(w_p) * (cos x - tan(w_p) sin x)
// => out = scale * prod_{p>=1} fmaf(-tan w_p, sin x, cos x), scale = prod cos w_p.
// Block = one 16-row segment x 64 cols, 128 threads = 64 cols x 2 ROW PARITIES.
// Even/odd split doubles total warps (8192, ~40 resident/SM) at ZERO extra
// fma work per output (each factor FFMA computed exactly once); only LDS/output
// doubles, which stays under the fma pipe. Parity is warp-uniform -> single
// top-level branch over two template instantiations (all inner checks static).
// Out-of-plane pixels are constant (cos,sin)=(1,0): no loads, no bounds math.
// Weights in __constant__ -> uniform-register FFMA operands (no GPR tax);
// prep writes directly into the constant backing store (2-node graph).

#define HW    64
#define PLANE (HW * HW)
#define TW    68   // 64 + 2*2 col halo
#define TR    20   // 16 + 2*2 row halo

__constant__ float c_w[26];   // [p]= -tan(w_p) (p=1..24), [25]= prod cos

__global__ void prep_kernel(const float* __restrict__ w, float* __restrict__ cw_store)
{
    __shared__ float cwsh[25];
    const int p = threadIdx.x;
    if (p < 25) {
        float s, c;
        sincosf(w[p], &s, &c);      // accurate; only 25 values
        cw_store[p] = -s / c;
        cwsh[p] = c;
    }
    __syncwarp();
    if (p == 0) {
        float sc = 1.0f;
#pragma unroll
        for (int q = 1; q < 25; ++q) sc *= cwsh[q];
        cw_store[25] = sc;
    }
}

// Walk the 20 tile rows; at walk row r, weight-row variant di feeds output
// o = r - di (segment-relative). This thread owns outputs with o&1 == PAR.
template<int PAR>
__device__ __forceinline__ void walk(const float2 (*scs)[TW], int j,
                                     float* op, int base, float scale)
{
    float acc[8];

#pragma unroll
    for (int r = 0; r < TR; ++r) {
        const float2 v0 = scs[r][j + 0];
        const float2 v1 = scs[r][j + 1];
        const float2 v2 = scs[r][j + 2];
        const float2 v3 = scs[r][j + 3];
        const float2 v4 = scs[r][j + 4];

#pragma unroll
        for (int di = 0; di < 5; ++di) {
            const int o = r - di;                  // output index in segment
            if (o < 0 || o >= 16) continue;
            if ((o & 1) != PAR) continue;          // compile-time parity select
            float h;
            if (di == 0) {
                // p = 0 (Z_0 wire) excluded: dj = 1..4 only.
                h = (fmaf(c_w[1], v1.y, v1.x) * fmaf(c_w[2], v2.y, v2.x))
                  * (fmaf(c_w[3], v3.y, v3.x) * fmaf(c_w[4], v4.y, v4.x));
            } else {
                const int b = di * 5;
                h = (fmaf(c_w[b    ], v0.y, v0.x) * fmaf(c_w[b + 1], v1.y, v1.x))
                  * (fmaf(c_w[b + 2], v2.y, v2.x) * fmaf(c_w[b + 3], v3.y, v3.x));
                h *= fmaf(c_w[b + 4], v4.y, v4.x);
            }
            const int k = o >> 1;
            acc[k] = (di == 0) ? h : acc[k] * h;
            if (di == 4)   // output complete -> store
                op[(base + o) * HW + j] = acc[k] * scale;
        }
    }
}

__global__ __launch_bounds__(128, 10)
void quanv_kernel(const float* __restrict__ x,
                  float* __restrict__ out)
{
    __shared__ float2 scs[TR][TW];   // (cos x, sin x); out-of-plane -> (1,0)

    const int blk   = blockIdx.x;
    const int plane = blk >> 2;
    const int seg   = blk & 3;            // 4 segments of 16 rows
    const int base  = seg * 16;           // first output row
    const float* xp = x + (size_t)plane * PLANE;
    float* op = out + (size_t)plane * PLANE;
    const int tid = threadIdx.x;

    // ---- Edge-column halo: cols {0,1,66,67} x 20 rows = 80 cells -> (1,0).
    if (tid < 80) {
        const int r  = tid >> 2;
        const int cc = tid & 3;
        const int c  = (cc < 2) ? cc : (64 + cc);
        scs[r][c] = make_float2(1.0f, 0.0f);
    }

    // ---- Interior cols 2..65: 20 rows x 16 float4 = 320 quads, 2-3/thread.
    // Out-of-plane rows (seg 0 top / seg 3 bottom) -> (1,0) constants.
    float4 xv[3];
    bool   real[3];
#pragma unroll
    for (int k = 0; k < 3; ++k) {
        const int q = tid + 128 * k;           // 0..383 (valid < 320)
        if (q < 320) {
            const int gr = base - 2 + (q >> 4);
            real[k] = (unsigned)gr < (unsigned)HW;
            if (real[k])
                xv[k] = *reinterpret_cast<const float4*>(xp + gr * HW + ((q & 15) << 2));
        }
    }
#pragma unroll
    for (int k = 0; k < 3; ++k) {
        const int q = tid + 128 * k;
        if (q < 320) {
            const int row = q >> 4;
            const int col = ((q & 15) << 2) + 2;
            if (real[k]) {
                float s, c;
                __sincosf(xv[k].x, &s, &c); scs[row][col + 0] = make_float2(c, s);
                __sincosf(xv[k].y, &s, &c); scs[row][col + 1] = make_float2(c, s);
                __sincosf(xv[k].z, &s, &c); scs[row][col + 2] = make_float2(c, s);
                __sincosf(xv[k].w, &s, &c); scs[row][col + 3] = make_float2(c, s);
            } else {
                const float2 one = make_float2(1.0f, 0.0f);
                scs[row][col + 0] = one; scs[row][col + 1] = one;
                scs[row][col + 2] = one; scs[row][col + 3] = one;
            }
        }
    }
    __syncthreads();

    const float scale = c_w[25];
    const int j   = tid & 63;     // column
    const int par = tid >> 6;     // row parity (warp-uniform: warps 0,1 / 2,3)

    if (par == 0) walk<0>(scs, j, op, base, scale);
    else          walk<1>(scs, j, op, base, scale);
}

extern "C" void kernel_launch(void* const* d_in, const int* in_sizes, int n_in,
                              void* d_out, int out_size)
{
    const float* x = (const float*)d_in[0];
    const float* w = (const float*)d_in[1];
    float* out = (float*)d_out;

    const int planes = in_sizes[0] / PLANE;   // B*C = 512

    // Device pointer to the __constant__ backing store (no allocation).
    void* cw_ptr = nullptr;
    cudaGetSymbolAddress(&cw_ptr, c_w);

    prep_kernel<<<1, 32>>>(w, (float*)cw_ptr);
    quanv_kernel<<<planes * 4, 128>>>(x, out);
}